// round 15
// baseline (speedup 1.0000x reference)
#include <cuda_runtime.h>
#include <cstdint>

#define HW 1024
#define PLANE (HW * HW)
#define BMAX 16

// Ping-pong scratch for the low-pass images (allocation-free rule).
static __device__ float g_lowA[BMAX * PLANE];
static __device__ float g_lowB[BMAX * PLANE];

__device__ __forceinline__ int refl(int i) {
    // jnp.pad 'symmetric': -1 -> 0, -2 -> 1, N -> N-1
    if (i < 0)   i = -1 - i;
    if (i >= HW) i = 2 * HW - 1 - i;
    return i;
}

__device__ __forceinline__ float4 rev4(const float4 v) {
    return make_float4(v.w, v.z, v.y, v.x);
}

__device__ __forceinline__ void cp16(float* dst_sm, const float* src_gm) {
    const unsigned sa = (unsigned)__cvta_generic_to_shared(dst_sm);
    asm volatile("cp.async.cg.shared.global [%0], [%1], 16;\n" :: "r"(sa), "l"(src_gm));
}
__device__ __forceinline__ void cp_commit() {
    asm volatile("cp.async.commit_group;\n");
}
template<int N> __device__ __forceinline__ void cp_wait() {
    asm volatile("cp.async.wait_group %0;\n" :: "n"(N));
}

// One starlet scale. Vertical dilated-by-D conv == plain 5-tap conv on each of
// D row-subsampled sub-images. Block = 256 threads = one full 1024-float row.
// blockIdx.y = residue, blockIdx.x = strip of S sub-rows, blockIdx.z = batch.
//
// Raw rows arrive via a cp.async ring: 4 slots x 2 rows in smem, each thread's
// own f4 column only (no cross-thread sync needed). One commit_group per slab;
// wait_group<1> before the vertical guarantees the needed pair landed while
// giving every load ~2 slabs of latency slack, register-free.
// Vertical results v0,v1 stay in registers as the horizontal center tap;
// reflected 16-float x-halo makes the horizontal pass branch-free (R13).
template<int D, int SRC, int DST>
__global__ __launch_bounds__(256, 4)
void starlet_stream(const float* __restrict__ ext_in,
                    const float* __restrict__ norms,
                    int scale,
                    float* __restrict__ coeff_out)
{
    constexpr int S = 32;                 // sub-rows per block
    constexpr int NSLAB = S / 2;          // 16
    constexpr int PAD = 16;               // halo floats per side (covers 2D<=16)
    constexpr int SMSV = PAD + HW + PAD + 4;
    constexpr float W0 = 1.0f / 16.0f;
    constexpr float W1 = 1.0f / 4.0f;
    constexpr float W2 = 3.0f / 8.0f;

    extern __shared__ __align__(16) float smem[];
    float* vb   = smem;                   // [2 buf][2 rows][SMSV]
    float* ring = smem + 4 * SMSV;        // [4 slots][2 rows][HW]

    const int t     = threadIdx.x;        // float4 column 0..255
    const int resid = blockIdx.y;
    const int s0    = blockIdx.x * S;
    const int b     = blockIdx.z;

    const float* src  = (SRC == 0) ? ext_in : (SRC == 1 ? g_lowA : g_lowB);
    const float* simg = src + (size_t)b * PLANE;
    float* lowdst = (DST == 1) ? g_lowA : (DST == 2 ? g_lowB : nullptr);
    if (DST != 0) lowdst += (size_t)b * PLANE;

    const int x4 = 4 * t;
    const int xb = PAD + x4;
    const float inv = 1.0f / norms[scale];
    const size_t step = (size_t)D * HW;

    auto vcomb = [](const float4& a, const float4& bb, const float4& c,
                    const float4& d, const float4& e) -> float4 {
        float4 v;
        v.x = W0 * (a.x + e.x) + W1 * (bb.x + d.x) + W2 * c.x;
        v.y = W0 * (a.y + e.y) + W1 * (bb.y + d.y) + W2 * c.y;
        v.z = W0 * (a.z + e.z) + W1 * (bb.z + d.z) + W2 * c.z;
        v.w = W0 * (a.w + e.w) + W1 * (bb.w + d.w) + W2 * c.w;
        return v;
    };

    // nextp() returns the global pointer (this thread's f4) of sub-rows
    // s0-2, s0-1, s0, ... in order; exactly S+4 calls.
    auto run = [&](auto&& nextp) {
        // ---- prolog: fill all 4 ring slots (pairs of rows), 4 commit groups ----
        #pragma unroll
        for (int p = 0; p < 4; p++) {
            cp16(ring + (2 * p + 0) * HW + x4, nextp());
            cp16(ring + (2 * p + 1) * HW + x4, nextp());
            cp_commit();
        }
        // prime window: rows s0-2..s0+1 live in slots 0,1
        cp_wait<2>();
        float4 w0 = *reinterpret_cast<const float4*>(ring + 0 * HW + x4);
        float4 w1 = *reinterpret_cast<const float4*>(ring + 1 * HW + x4);
        float4 w2 = *reinterpret_cast<const float4*>(ring + 2 * HW + x4);
        float4 w3 = *reinterpret_cast<const float4*>(ring + 3 * HW + x4);

        float* cp_ = coeff_out + ((size_t)b * HW + (size_t)(resid + D * s0)) * HW + x4;
        float* lp  = (DST != 0) ? lowdst + (size_t)(resid + D * s0) * HW + x4 : nullptr;

        #pragma unroll 4
        for (int i = 0; i < NSLAB; i++) {
            // ---- wait for this slab's n-pair (2 slabs of slack per load) ----
            cp_wait<1>();
            const int rs = (i + 2) & 3;
            const float4 n0 = *reinterpret_cast<const float4*>(ring + (2 * rs + 0) * HW + x4);
            const float4 n1 = *reinterpret_cast<const float4*>(ring + (2 * rs + 1) * HW + x4);

            const int buf = i & 1;
            float* v0row = vb + (2 * buf + 0) * SMSV;
            float* v1row = vb + (2 * buf + 1) * SMSV;

            // ---- vertical 5-tap; results stay in regs as horizontal centers ----
            const float4 v0 = vcomb(w0, w1, w2, w3, n0);
            const float4 v1 = vcomb(w1, w2, w3, n0, n1);
            *reinterpret_cast<float4*>(v0row + xb) = v0;
            *reinterpret_cast<float4*>(v1row + xb) = v1;

            // reflected x-halo (branch-free horizontal below)
            if (t < 4) {
                const int o = PAD - 4 * (t + 1);
                *reinterpret_cast<float4*>(v0row + o) = rev4(v0);
                *reinterpret_cast<float4*>(v1row + o) = rev4(v1);
            } else if (t >= 252) {
                const int o = PAD + HW + 4 * (255 - t);
                *reinterpret_cast<float4*>(v0row + o) = rev4(v0);
                *reinterpret_cast<float4*>(v1row + o) = rev4(v1);
            }

            // shift window (raw centers become new w0,w1)
            w0 = w2; w1 = w3; w2 = n0; w3 = n1;

            // ---- issue next pair into slot (i&3); one commit per slab ----
            if (i <= NSLAB - 3) {
                const int ws = i & 3;
                cp16(ring + (2 * ws + 0) * HW + x4, nextp());
                cp16(ring + (2 * ws + 1) * HW + x4, nextp());
            }
            cp_commit();

            __syncthreads();

            // ---- horizontal 5-tap (dilated by D): uniform, branch-free ----
            #pragma unroll
            for (int r = 0; r < 2; r++) {
                const float* smrow = (r == 0) ? v0row : v1row;
                const float4 vc  = (r == 0) ? v0 : v1;
                const float4 raw = (r == 0) ? w0 : w1;
                float4 low;

                if constexpr (D >= 4) {
                    constexpr int G = D / 4;
                    const float4 a  = *reinterpret_cast<const float4*>(&smrow[xb - 8 * G]);
                    const float4 bb = *reinterpret_cast<const float4*>(&smrow[xb - 4 * G]);
                    const float4 d  = *reinterpret_cast<const float4*>(&smrow[xb + 4 * G]);
                    const float4 e  = *reinterpret_cast<const float4*>(&smrow[xb + 8 * G]);
                    low = vcomb(a, bb, vc, d, e);
                } else {
                    float fl[12];
                    *reinterpret_cast<float4*>(&fl[0]) = *reinterpret_cast<const float4*>(&smrow[xb - 4]);
                    fl[4] = vc.x; fl[5] = vc.y; fl[6] = vc.z; fl[7] = vc.w;
                    *reinterpret_cast<float4*>(&fl[8]) = *reinterpret_cast<const float4*>(&smrow[xb + 4]);
                    float lo[4];
                    #pragma unroll
                    for (int j = 0; j < 4; j++) {
                        lo[j] = W0 * (fl[4 + j - 2 * D] + fl[4 + j + 2 * D])
                              + W1 * (fl[4 + j - D]     + fl[4 + j + D])
                              + W2 *  fl[4 + j];
                    }
                    low.x = lo[0]; low.y = lo[1]; low.z = lo[2]; low.w = lo[3];
                }

                float4 cf;
                cf.x = (raw.x - low.x) * inv;
                cf.y = (raw.y - low.y) * inv;
                cf.z = (raw.z - low.z) * inv;
                cf.w = (raw.w - low.w) * inv;

                __stcs(reinterpret_cast<float4*>(cp_), cf);   // streaming store
                cp_ += step;
                if (DST != 0) {
                    *reinterpret_cast<float4*>(lp) = low;     // keep in L2
                    lp += step;
                }
            }
            // double-buffered v-smem: no trailing barrier
        }
    };

    const int HWsub = HW / D;
    if (s0 >= 2 && s0 + S + 2 <= HWsub) {
        // interior strip: pure incremental pointer, no reflection possible
        const float* p = simg + (size_t)(resid + D * (s0 - 2)) * HW + x4;
        run([&]() -> const float* {
            const float* r = p;
            p += step;
            return r;
        });
    } else {
        // boundary strip: reflected row indices
        int s = s0 - 2;
        run([&]() -> const float* {
            const int f = refl(resid + D * s);
            s++;
            return simg + (size_t)f * HW + x4;
        });
    }
}

static constexpr int SMEM_BYTES = (4 * (16 + HW + 16 + 4) + 8 * HW) * 4;  // 49728

extern "C" void kernel_launch(void* const* d_in, const int* in_sizes, int n_in,
                              void* d_out, int out_size)
{
    int img_idx = 0, nrm_idx = 1;
    if (n_in >= 2 && in_sizes[0] == 4) { img_idx = 1; nrm_idx = 0; }

    const float* image = (const float*)d_in[img_idx];
    const float* norms = (const float*)d_in[nrm_idx];
    float* out = (float*)d_out;

    int B = in_sizes[img_idx] / PLANE;
    if (B < 1) B = 1;
    if (B > BMAX) B = BMAX;
    const size_t plane_all = (size_t)B * PLANE;

    // Raise dynamic-smem limit (49.7 KB/CTA; 4 CTAs/SM = 199 KB < 227 KB).
    cudaFuncSetAttribute(starlet_stream<1, 0, 1>, cudaFuncAttributeMaxDynamicSharedMemorySize, SMEM_BYTES);
    cudaFuncSetAttribute(starlet_stream<2, 1, 2>, cudaFuncAttributeMaxDynamicSharedMemorySize, SMEM_BYTES);
    cudaFuncSetAttribute(starlet_stream<4, 2, 1>, cudaFuncAttributeMaxDynamicSharedMemorySize, SMEM_BYTES);
    cudaFuncSetAttribute(starlet_stream<8, 1, 0>, cudaFuncAttributeMaxDynamicSharedMemorySize, SMEM_BYTES);

    const dim3 block(256);
    // grid: x = strips of 32 sub-rows, y = D residues, z = batch (512 blocks/scale)
    const dim3 g1(HW / (1 * 32), 1, B);
    const dim3 g2(HW / (2 * 32), 2, B);
    const dim3 g4(HW / (4 * 32), 4, B);
    const dim3 g8(HW / (8 * 32), 8, B);

    starlet_stream<1, 0, 1><<<g1, block, SMEM_BYTES>>>(image, norms, 0, out + 0 * plane_all);
    starlet_stream<2, 1, 2><<<g2, block, SMEM_BYTES>>>(image, norms, 1, out + 1 * plane_all);
    starlet_stream<4, 2, 1><<<g4, block, SMEM_BYTES>>>(image, norms, 2, out + 2 * plane_all);
    starlet_stream<8, 1, 0><<<g8, block, SMEM_BYTES>>>(image, norms, 3, out + 3 * plane_all);
}